// round 2
// baseline (speedup 1.0000x reference)
#include <cuda_runtime.h>

// Fused edge-MLP cross-entropy loss.
//   X[e] = concat(feature[row[e]], feature[col[e]])  (K = 256)
//   h = PReLU(X @ W1 + b1)                           (N = 128)
//   logits = h @ W2 + b2                             (2 classes)
//   loss = -mean_e logsoftmax(logits)[y_e],  y_e = (label[row]==label[col])
//
// NOTE: row/col/label arrive as int32 (JAX x64 disabled downcasts int64).
//
// Block = 64 edges. W1 (128 KB) + transposed X tile (~67 KB) in smem.
// Warp <-> 8 edges, lane <-> 4 output channels. Epilogue fully fused.

namespace {
constexpr int NHID      = 128;
constexpr int KDIM      = 256;
constexpr int TILE_E    = 64;
constexpr int XS_STRIDE = 66;   // floats; 8B-aligned rows, 2-way store conflicts only
constexpr int THREADS   = 256;
constexpr int SMEM_BYTES = (KDIM * NHID + KDIM * XS_STRIDE) * (int)sizeof(float);
}

__device__ double g_loss_sum;

__global__ void hx_init_kernel() { g_loss_sum = 0.0; }

__global__ void hx_final_kernel(float* out, int E) {
    out[0] = (float)(-g_loss_sum / (double)E);
}

__global__ __launch_bounds__(THREADS, 1)
void hx_main_kernel(const float* __restrict__ feature,
                    const float* __restrict__ W1,
                    const float* __restrict__ b1,
                    const float* __restrict__ alpha,
                    const float* __restrict__ W2,
                    const float* __restrict__ b2,
                    const int* __restrict__ row,
                    const int* __restrict__ col,
                    const int* __restrict__ label,
                    int E)
{
    extern __shared__ float sm[];
    float* W1s = sm;                 // [KDIM][NHID] row-major (k, c)
    float* Xs  = sm + KDIM * NHID;   // [KDIM][XS_STRIDE] transposed X tile (k, e)
    __shared__ float s_bsum;

    const int tid  = threadIdx.x;
    const int lane = tid & 31;
    const int warp = tid >> 5;
    if (tid == 0) s_bsum = 0.0f;

    // ---- Stage W1 into smem (coalesced float4) ----
    {
        const float4* W1v  = reinterpret_cast<const float4*>(W1);
        float4*       W1sv = reinterpret_cast<float4*>(W1s);
        for (int i = tid; i < KDIM * NHID / 4; i += THREADS)
            W1sv[i] = W1v[i];
    }

    // ---- Gather X tile (transposed: Xs[k][e]) ----
    // warp w loads edges w*8 .. w*8+7; lane = k offset within a 32-chunk
    // (coalesced LDG from L2-resident feature table; conflict-light STS).
    const int ebase = blockIdx.x * TILE_E;
    for (int j = 0; j < 8; ++j) {
        int el = warp * 8 + j;
        int e  = ebase + el;
        if (e >= E) e = 0;  // safe dup; masked in epilogue
        const int r = row[e];
        const int c = col[e];
        const float* fr = feature + (size_t)r * NHID;
        const float* fc = feature + (size_t)c * NHID;
        #pragma unroll
        for (int kb = 0; kb < 4; ++kb)
            Xs[(kb * 32 + lane) * XS_STRIDE + el] = fr[kb * 32 + lane];
        #pragma unroll
        for (int kb = 0; kb < 4; ++kb)
            Xs[(NHID + kb * 32 + lane) * XS_STRIDE + el] = fc[kb * 32 + lane];
    }
    __syncthreads();

    // ---- Register-tiled GEMM: 8 edges x 4 channels per thread ----
    const int e0 = warp * 8;
    const int c0 = lane * 4;

    float acc[8][4];
    #pragma unroll
    for (int i = 0; i < 8; ++i) {
        acc[i][0] = 0.f; acc[i][1] = 0.f; acc[i][2] = 0.f; acc[i][3] = 0.f;
    }

    #pragma unroll 4
    for (int k = 0; k < KDIM; ++k) {
        const float4 w = *reinterpret_cast<const float4*>(&W1s[k * NHID + c0]);
        const float* xr = &Xs[k * XS_STRIDE + e0];
        // warp-uniform addresses -> smem broadcast (conflict-free)
        const float2 xa = *reinterpret_cast<const float2*>(xr + 0);
        const float2 xb = *reinterpret_cast<const float2*>(xr + 2);
        const float2 xc = *reinterpret_cast<const float2*>(xr + 4);
        const float2 xd = *reinterpret_cast<const float2*>(xr + 6);
        const float x[8] = {xa.x, xa.y, xb.x, xb.y, xc.x, xc.y, xd.x, xd.y};
        #pragma unroll
        for (int i = 0; i < 8; ++i) {
            acc[i][0] = fmaf(x[i], w.x, acc[i][0]);
            acc[i][1] = fmaf(x[i], w.y, acc[i][1]);
            acc[i][2] = fmaf(x[i], w.z, acc[i][2]);
            acc[i][3] = fmaf(x[i], w.w, acc[i][3]);
        }
    }

    // ---- Fused epilogue: bias + PReLU + (128->2) + log-softmax + NLL ----
    const float4 b1v = *reinterpret_cast<const float4*>(&b1[c0]);
    const float4 av  = *reinterpret_cast<const float4*>(&alpha[c0]);
    // W2 is [128,2] row-major: W2[(c0+j)*2 + t]
    const float4 w2a = *reinterpret_cast<const float4*>(&W2[c0 * 2]);
    const float4 w2b = *reinterpret_cast<const float4*>(&W2[c0 * 2 + 4]);
    const float w20[4] = {w2a.x, w2a.z, w2b.x, w2b.z};
    const float w21[4] = {w2a.y, w2a.w, w2b.y, w2b.w};
    const float bb1[4] = {b1v.x, b1v.y, b1v.z, b1v.w};
    const float aa[4]  = {av.x,  av.y,  av.z,  av.w};
    const float bias0 = b2[0], bias1 = b2[1];

    float warp_logp = 0.0f;
    #pragma unroll
    for (int i = 0; i < 8; ++i) {
        float p0 = 0.f, p1 = 0.f;
        #pragma unroll
        for (int j = 0; j < 4; ++j) {
            float h = acc[i][j] + bb1[j];
            h = (h >= 0.f) ? h : aa[j] * h;
            p0 = fmaf(h, w20[j], p0);
            p1 = fmaf(h, w21[j], p1);
        }
        #pragma unroll
        for (int off = 16; off > 0; off >>= 1) {
            p0 += __shfl_xor_sync(0xffffffffu, p0, off);
            p1 += __shfl_xor_sync(0xffffffffu, p1, off);
        }
        if (lane == 0) {
            const int e = ebase + e0 + i;
            if (e < E) {
                const int r = row[e];
                const int c = col[e];
                const int y = (label[r] == label[c]) ? 1 : 0;
                const float l0 = p0 + bias0;
                const float l1 = p1 + bias1;
                const float m  = fmaxf(l0, l1);
                const float lse = m + log1pf(expf(-fabsf(l0 - l1)));
                const float ly  = y ? l1 : l0;
                warp_logp += ly - lse;
            }
        }
    }

    if (lane == 0) atomicAdd(&s_bsum, warp_logp);
    __syncthreads();
    if (tid == 0) atomicAdd(&g_loss_sum, (double)s_bsum);
}

extern "C" void kernel_launch(void* const* d_in, const int* in_sizes, int n_in,
                              void* d_out, int out_size) {
    const float* feature = (const float*)d_in[0];
    const float* W1      = (const float*)d_in[1];
    const float* b1      = (const float*)d_in[2];
    const float* alpha   = (const float*)d_in[3];
    const float* W2      = (const float*)d_in[4];
    const float* b2      = (const float*)d_in[5];
    const int*   row     = (const int*)d_in[6];
    const int*   col     = (const int*)d_in[7];
    const int*   label   = (const int*)d_in[8];
    const int E = in_sizes[6];
    float* out = (float*)d_out;

    // Executes immediately (not a stream op) — safe under graph capture.
    cudaFuncSetAttribute(hx_main_kernel,
                         cudaFuncAttributeMaxDynamicSharedMemorySize, SMEM_BYTES);

    hx_init_kernel<<<1, 1>>>();
    const int grid = (E + TILE_E - 1) / TILE_E;
    hx_main_kernel<<<grid, THREADS, SMEM_BYTES>>>(
        feature, W1, b1, alpha, W2, b2, row, col, label, E);
    hx_final_kernel<<<1, 1>>>(out, E);
}

// round 4
// speedup vs baseline: 4.9020x; 4.9020x over previous
#include <cuda_runtime.h>
#include <cuda_bf16.h>
#include <cstdint>

// Fused edge-MLP CE loss via warp-level bf16 mma.sync (tensor cores, no "a"-arch features).
//   prep: feature fp32 -> bf16 table; W1 fp32 -> bf16 smem-image (ldmatrix swizzle)
//   main: persistent CTAs; per tile (128 edges):
//         cp.async gather (double-buffered, swizzled) -> ldmatrix + mma.sync.m16n8k16
//         -> fused PReLU / W2 / log-softmax / NLL epilogue. Prefetch overlaps compute.

namespace {
constexpr int NHID    = 128;
constexpr int KDIM    = 256;
constexpr int TILE_E  = 128;
constexpr int THREADS = 256;
constexpr int A_BYTES = TILE_E * KDIM * 2;   // 64 KB per A buffer (swizzled rows of 512B)
constexpr int B_BYTES = KDIM * NHID * 2;     // 64 KB W1 image (swizzled rows of 256B)
constexpr int DSMEM   = B_BYTES + 2 * A_BYTES + 256;
}

__device__ __align__(16) __nv_bfloat16 g_feat_bf16[(size_t)100000 * NHID];
__device__ __align__(16) __nv_bfloat16 g_w1_img[KDIM * NHID];
__device__ double g_loss_sum;

__device__ __forceinline__ uint32_t smem_u32(const void* p) {
    uint32_t a;
    asm("{ .reg .u64 t; cvta.to.shared.u64 t, %1; cvt.u32.u64 %0, t; }" : "=r"(a) : "l"(p));
    return a;
}

// ---------------- prep kernels ----------------
__global__ void hx_init_kernel() { g_loss_sum = 0.0; }

__global__ void hx_prep_feat(const float* __restrict__ f, int n4) {
    int i = blockIdx.x * blockDim.x + threadIdx.x;
    if (i < n4) {
        float4 v = reinterpret_cast<const float4*>(f)[i];
        __nv_bfloat162* dst = reinterpret_cast<__nv_bfloat162*>(g_feat_bf16);
        dst[i * 2]     = __floats2bfloat162_rn(v.x, v.y);
        dst[i * 2 + 1] = __floats2bfloat162_rn(v.z, v.w);
    }
}

// W1 [in=256(k), out=128(n)] row-major -> smem image: row k = 256B (16 chunks of 16B),
// chunk c = n>>3 stored at c' = (c&8) | ((c&7) ^ (k&7)); element (n&7) inside chunk.
__global__ void hx_prep_w1(const float* __restrict__ W1) {
    int idx = blockIdx.x * blockDim.x + threadIdx.x;   // 32768
    int k = idx >> 7, n = idx & 127;
    int c = n >> 3;
    int cs = (c & 8) | ((c & 7) ^ (k & 7));
    uint32_t off = (uint32_t)k * 256u + (uint32_t)cs * 16u + (uint32_t)(n & 7) * 2u;
    *reinterpret_cast<__nv_bfloat16*>(reinterpret_cast<char*>(g_w1_img) + off) =
        __float2bfloat16(W1[idx]);
}

__global__ void hx_final_kernel(float* out, int E) {
    out[0] = (float)(-g_loss_sum / (double)E);
}

// ---------------- gather (cp.async) ----------------
// A tile: 128 rows (edges) x 256 bf16 (k). Row = 512B = 32 chunks of 16B.
// chunk c at c' = (c&24) | ((c&7) ^ (row&7)).
__device__ __forceinline__ void gather_tile(
    uint32_t Abuf, int t, int E,
    const int* __restrict__ row, const int* __restrict__ col,
    const int* __restrict__ label, int (*s_lab)[TILE_E], int el, int h)
{
    int e = t * TILE_E + el;
    if (e >= E) e = 0;                       // duplicate; masked in epilogue
    const int node = h ? col[e] : row[e];
    s_lab[h][el] = label[node];
    const char* src = reinterpret_cast<const char*>(g_feat_bf16) + (size_t)node * 256;
    const uint32_t rowbase = Abuf + (uint32_t)el * 512u;
    const int x = el & 7;
    #pragma unroll
    for (int i = 0; i < 16; ++i) {
        const int c  = h * 16 + i;
        const int cs = (c & 24) | ((c & 7) ^ x);
        asm volatile("cp.async.cg.shared.global [%0], [%1], 16;"
                     :: "r"(rowbase + (uint32_t)cs * 16u), "l"(src + i * 16) : "memory");
    }
}

// ---------------- main persistent kernel ----------------
__global__ __launch_bounds__(THREADS, 1)
void hx_main_kernel(const float* __restrict__ b1,
                    const float* __restrict__ alpha,
                    const float* __restrict__ W2,
                    const float* __restrict__ b2,
                    const int* __restrict__ row,
                    const int* __restrict__ col,
                    const int* __restrict__ label,
                    int E, int ntiles)
{
    extern __shared__ char dyn[];
    __shared__ float s_b1[NHID], s_al[NHID], s_w20[NHID], s_w21[NHID];
    __shared__ float s_p0[TILE_E], s_p1[TILE_E];
    __shared__ int   s_lab[2][2][TILE_E];
    __shared__ double s_dsum;

    const int tid  = threadIdx.x;
    const int lane = tid & 31;
    const int warp = tid >> 5;

    const uint32_t dynb = smem_u32(dyn);
    const uint32_t base = (dynb + 255u) & ~255u;
    const uint32_t Bsm  = base;
    const uint32_t Asm0 = base + B_BYTES;

    if (tid == 0) s_dsum = 0.0;
    if (tid < NHID) {
        s_b1[tid]  = b1[tid];
        s_al[tid]  = alpha[tid];
        s_w20[tid] = W2[2 * tid];
        s_w21[tid] = W2[2 * tid + 1];
    }
    {   // stage W1 image (linear 64 KB copy)
        char* dst = dyn + (base - dynb);
        const int4* s = reinterpret_cast<const int4*>(g_w1_img);
        int4* d = reinterpret_cast<int4*>(dst);
        for (int i = tid; i < B_BYTES / 16; i += THREADS) d[i] = s[i];
    }

    const float bias0 = b2[0], bias1 = b2[1];
    const int g_el = tid >> 1, g_h = tid & 1;

    // warp tile: 2 (M halves of 64) x 4 (N strips of 32)
    const int warp_m = warp & 1, warp_n = warp >> 1;
    const int m_base = warp_m * 64, n_base = warp_n * 32;

    // A ldmatrix row bases: lane -> row m_base + i*16 + (lane&15), chunk half = lane>>4
    uint32_t rowA[4]; int xA[4];
    #pragma unroll
    for (int i = 0; i < 4; ++i) {
        const int r = m_base + i * 16 + (lane & 15);
        rowA[i] = (uint32_t)r * 512u;
        xA[i]   = r & 7;
    }
    const int csA = lane >> 4;

    // B ldmatrix thread bases (x4.trans): row k0+(lane&15), chunk cn = n_base/8 + j2*2 + (lane>>4)
    uint32_t bBase[2];
    {
        const int kr = lane & 15;
        const int xB = lane & 7;
        #pragma unroll
        for (int j2 = 0; j2 < 2; ++j2) {
            const int cn = warp_n * 4 + j2 * 2 + (lane >> 4);
            const int cs = (cn & 8) | ((cn & 7) ^ xB);
            bBase[j2] = Bsm + (uint32_t)kr * 256u + (uint32_t)cs * 16u;
        }
    }

    double dsum = 0.0;
    int li = 0;

    if (blockIdx.x < ntiles) {
        gather_tile(Asm0, blockIdx.x, E, row, col, label, s_lab[0], g_el, g_h);
        asm volatile("cp.async.commit_group;" ::: "memory");
    }

    for (int t = blockIdx.x; t < ntiles; t += gridDim.x, ++li) {
        const int buf = li & 1;
        const uint32_t Abuf = Asm0 + (uint32_t)buf * A_BYTES;
        const int tn = t + gridDim.x;
        if (tn < ntiles) {
            gather_tile(Asm0 + (uint32_t)(buf ^ 1) * A_BYTES, tn, E,
                        row, col, label, s_lab[buf ^ 1], g_el, g_h);
            asm volatile("cp.async.commit_group;" ::: "memory");
            asm volatile("cp.async.wait_group 1;" ::: "memory");
        } else {
            asm volatile("cp.async.wait_group 0;" ::: "memory");
        }
        __syncthreads();

        // ---- GEMM: 16 k-steps of m16n8k16 ----
        float acc[4][4][4];
        #pragma unroll
        for (int i = 0; i < 4; ++i)
            #pragma unroll
            for (int j = 0; j < 4; ++j) {
                acc[i][j][0] = 0.f; acc[i][j][1] = 0.f;
                acc[i][j][2] = 0.f; acc[i][j][3] = 0.f;
            }

        #pragma unroll
        for (int ks = 0; ks < 16; ++ks) {
            uint32_t a[4][4];
            #pragma unroll
            for (int i = 0; i < 4; ++i) {
                const int c  = 2 * ks + csA;
                const int cs = (c & 24) | ((c & 7) ^ xA[i]);
                const uint32_t addr = Abuf + rowA[i] + (uint32_t)cs * 16u;
                asm volatile("ldmatrix.sync.aligned.m8n8.x4.shared.b16 {%0,%1,%2,%3}, [%4];"
                    : "=r"(a[i][0]), "=r"(a[i][1]), "=r"(a[i][2]), "=r"(a[i][3]) : "r"(addr));
            }
            uint32_t b[2][4];
            #pragma unroll
            for (int j2 = 0; j2 < 2; ++j2) {
                const uint32_t addr = bBase[j2] + (uint32_t)ks * 4096u;
                asm volatile("ldmatrix.sync.aligned.m8n8.x4.trans.shared.b16 {%0,%1,%2,%3}, [%4];"
                    : "=r"(b[j2][0]), "=r"(b[j2][1]), "=r"(b[j2][2]), "=r"(b[j2][3]) : "r"(addr));
            }
            #pragma unroll
            for (int i = 0; i < 4; ++i)
                #pragma unroll
                for (int j = 0; j < 4; ++j) {
                    const uint32_t bb0 = b[j >> 1][(j & 1) * 2];
                    const uint32_t bb1 = b[j >> 1][(j & 1) * 2 + 1];
                    asm volatile(
                        "mma.sync.aligned.m16n8k16.row.col.f32.bf16.bf16.f32 "
                        "{%0,%1,%2,%3}, {%4,%5,%6,%7}, {%8,%9}, {%0,%1,%2,%3};"
                        : "+f"(acc[i][j][0]), "+f"(acc[i][j][1]),
                          "+f"(acc[i][j][2]), "+f"(acc[i][j][3])
                        : "r"(a[i][0]), "r"(a[i][1]), "r"(a[i][2]), "r"(a[i][3]),
                          "r"(bb0), "r"(bb1));
                }
        }

        __syncthreads();                                   // all warps done with Abuf
        if (tid < TILE_E) { s_p0[tid] = 0.f; s_p1[tid] = 0.f; }
        __syncthreads();

        // ---- fragment epilogue: PReLU + 128->2 projection ----
        const int quad = lane >> 2, qlane = lane & 3;
        float pr0[8], pr1[8];
        #pragma unroll
        for (int i = 0; i < 8; ++i) { pr0[i] = 0.f; pr1[i] = 0.f; }

        #pragma unroll
        for (int j = 0; j < 4; ++j) {
            const int n = n_base + j * 8 + qlane * 2;
            const float bv0 = s_b1[n],  bv1 = s_b1[n + 1];
            const float av0 = s_al[n],  av1 = s_al[n + 1];
            const float wa0 = s_w20[n], wa1 = s_w20[n + 1];
            const float wb0 = s_w21[n], wb1 = s_w21[n + 1];
            #pragma unroll
            for (int i = 0; i < 4; ++i) {
                float h;
                h = acc[i][j][0] + bv0; h = h >= 0.f ? h : av0 * h;
                pr0[i*2]   = fmaf(h, wa0, pr0[i*2]);   pr1[i*2]   = fmaf(h, wb0, pr1[i*2]);
                h = acc[i][j][1] + bv1; h = h >= 0.f ? h : av1 * h;
                pr0[i*2]   = fmaf(h, wa1, pr0[i*2]);   pr1[i*2]   = fmaf(h, wb1, pr1[i*2]);
                h = acc[i][j][2] + bv0; h = h >= 0.f ? h : av0 * h;
                pr0[i*2+1] = fmaf(h, wa0, pr0[i*2+1]); pr1[i*2+1] = fmaf(h, wb0, pr1[i*2+1]);
                h = acc[i][j][3] + bv1; h = h >= 0.f ? h : av1 * h;
                pr0[i*2+1] = fmaf(h, wa1, pr0[i*2+1]); pr1[i*2+1] = fmaf(h, wb1, pr1[i*2+1]);
            }
        }
        #pragma unroll
        for (int i = 0; i < 8; ++i) {
            pr0[i] += __shfl_xor_sync(0xffffffffu, pr0[i], 1);
            pr0[i] += __shfl_xor_sync(0xffffffffu, pr0[i], 2);
            pr1[i] += __shfl_xor_sync(0xffffffffu, pr1[i], 1);
            pr1[i] += __shfl_xor_sync(0xffffffffu, pr1[i], 2);
        }
        if (qlane == 0) {
            #pragma unroll
            for (int i = 0; i < 4; ++i) {
                const int r0 = m_base + i * 16 + quad;
                atomicAdd(&s_p0[r0],     pr0[i*2]);   atomicAdd(&s_p1[r0],     pr1[i*2]);
                atomicAdd(&s_p0[r0 + 8], pr0[i*2+1]); atomicAdd(&s_p1[r0 + 8], pr1[i*2+1]);
            }
        }
        __syncthreads();

        // ---- per-edge log-softmax + NLL ----
        if (tid < TILE_E) {
            const int e = t * TILE_E + tid;
            if (e < E) {
                const float l0 = s_p0[tid] + bias0;
                const float l1 = s_p1[tid] + bias1;
                const int y   = (s_lab[buf][0][tid] == s_lab[buf][1][tid]);
                const float mx  = fmaxf(l0, l1);
                const float lse = mx + log1pf(expf(-fabsf(l0 - l1)));
                dsum += (double)((y ? l1 : l0) - lse);
            }
        }
    }

    __syncthreads();
    if (tid < TILE_E) atomicAdd(&s_dsum, dsum);
    __syncthreads();
    if (tid == 0) atomicAdd(&g_loss_sum, s_dsum);
}

extern "C" void kernel_launch(void* const* d_in, const int* in_sizes, int n_in,
                              void* d_out, int out_size) {
    const float* feature = (const float*)d_in[0];
    const float* W1      = (const float*)d_in[1];
    const float* b1      = (const float*)d_in[2];
    const float* alpha   = (const float*)d_in[3];
    const float* W2      = (const float*)d_in[4];
    const float* b2      = (const float*)d_in[5];
    const int*   row     = (const int*)d_in[6];
    const int*   col     = (const int*)d_in[7];
    const int*   label   = (const int*)d_in[8];
    const int E  = in_sizes[6];
    const int nf = in_sizes[0];
    float* out = (float*)d_out;

    int sms = 148;
    cudaDeviceGetAttribute(&sms, cudaDevAttrMultiProcessorCount, 0);
    cudaFuncSetAttribute(hx_main_kernel,
                         cudaFuncAttributeMaxDynamicSharedMemorySize, DSMEM);

    hx_init_kernel<<<1, 1>>>();
    hx_prep_feat<<<(nf / 4 + 255) / 256, 256>>>(feature, nf / 4);
    hx_prep_w1<<<(KDIM * NHID) / 256, 256>>>(W1);

    const int ntiles = (E + TILE_E - 1) / TILE_E;
    hx_main_kernel<<<sms, THREADS, DSMEM>>>(b1, alpha, W2, b2, row, col, label, E, ntiles);
    hx_final_kernel<<<1, 1>>>(out, E);
}

// round 5
// speedup vs baseline: 5.4081x; 1.1032x over previous
#include <cuda_runtime.h>
#include <cuda_bf16.h>
#include <cstdint>

// Fused edge-MLP CE loss via warp-level bf16 mma.sync.
// R5: 512 threads (4x4 warp grid, m32n32 warp tiles), index/label prefetch
// pipeline (no exposed LDG chain at tile top), atomic-free 2-barrier epilogue.

namespace {
constexpr int NHID    = 128;
constexpr int KDIM    = 256;
constexpr int TILE_E  = 128;
constexpr int THREADS = 512;
constexpr int A_BYTES = TILE_E * KDIM * 2;   // 64 KB per A buffer (rows of 512B, swizzled)
constexpr int B_BYTES = KDIM * NHID * 2;     // 64 KB W1 image (rows of 256B, swizzled)
constexpr int DSMEM   = B_BYTES + 2 * A_BYTES + 256;
}

__device__ __align__(16) __nv_bfloat16 g_feat_bf16[(size_t)100000 * NHID];
__device__ __align__(16) __nv_bfloat16 g_w1_img[KDIM * NHID];
__device__ double g_loss_sum;

__device__ __forceinline__ uint32_t smem_u32(const void* p) {
    uint32_t a;
    asm("{ .reg .u64 t; cvta.to.shared.u64 t, %1; cvt.u32.u64 %0, t; }" : "=r"(a) : "l"(p));
    return a;
}

// ---------------- prep kernels ----------------
__global__ void hx_init_kernel() { g_loss_sum = 0.0; }

__global__ void hx_prep_feat(const float* __restrict__ f, int n4) {
    int i = blockIdx.x * blockDim.x + threadIdx.x;
    if (i < n4) {
        float4 v = reinterpret_cast<const float4*>(f)[i];
        __nv_bfloat162* dst = reinterpret_cast<__nv_bfloat162*>(g_feat_bf16);
        dst[i * 2]     = __floats2bfloat162_rn(v.x, v.y);
        dst[i * 2 + 1] = __floats2bfloat162_rn(v.z, v.w);
    }
}

// W1 [k=256, n=128] row-major -> image: row k = 256B (16 chunks of 16B),
// chunk c = n>>3 at c' = (c&8) | ((c&7) ^ (k&7)).
__global__ void hx_prep_w1(const float* __restrict__ W1) {
    int idx = blockIdx.x * blockDim.x + threadIdx.x;   // 32768
    int k = idx >> 7, n = idx & 127;
    int c = n >> 3;
    int cs = (c & 8) | ((c & 7) ^ (k & 7));
    uint32_t off = (uint32_t)k * 256u + (uint32_t)cs * 16u + (uint32_t)(n & 7) * 2u;
    *reinterpret_cast<__nv_bfloat16*>(reinterpret_cast<char*>(g_w1_img) + off) =
        __float2bfloat16(W1[idx]);
}

__global__ void hx_final_kernel(float* out, int E) {
    out[0] = (float)(-g_loss_sum / (double)E);
}

// ---------------- device helpers ----------------
// Thread gather identity: el = tid>>2 (edge in tile), rem = tid&3,
// h = rem>>1 (row/col half), part = rem&1 (which 8 of 16 chunks).
__device__ __forceinline__ void prefetch_idx(
    int t, int E, const int* __restrict__ row, const int* __restrict__ col,
    const int* __restrict__ label, int el, int h, int rem, int& nid, int& yv)
{
    int e = t * TILE_E + el;
    if (e >= E) e = 0;
    const int r = row[e];
    const int c = col[e];
    nid = h ? c : r;
    yv = 0;
    if (rem == 0) yv = (label[r] == label[c]) ? 1 : 0;
}

__device__ __forceinline__ void gather_issue(uint32_t Abuf, int nid,
                                             int el, int h, int part)
{
    const char* src = reinterpret_cast<const char*>(g_feat_bf16) + (size_t)nid * 256;
    const uint32_t rowbase = Abuf + (uint32_t)el * 512u;
    const int x = el & 7;
    #pragma unroll
    for (int ii = 0; ii < 8; ++ii) {
        const int i  = part * 8 + ii;
        const int c  = h * 16 + i;
        const int cs = (c & 24) | ((c & 7) ^ x);
        asm volatile("cp.async.cg.shared.global [%0], [%1], 16;"
                     :: "r"(rowbase + (uint32_t)cs * 16u), "l"(src + i * 16) : "memory");
    }
}

// ---------------- main persistent kernel ----------------
__global__ __launch_bounds__(THREADS, 1)
void hx_main_kernel(const float* __restrict__ b1,
                    const float* __restrict__ alpha,
                    const float* __restrict__ W2,
                    const float* __restrict__ b2,
                    const int* __restrict__ row,
                    const int* __restrict__ col,
                    const int* __restrict__ label,
                    int E, int ntiles)
{
    extern __shared__ char dyn[];
    __shared__ float s_b1[NHID], s_al[NHID], s_w20[NHID], s_w21[NHID];
    __shared__ float s_part0[4][TILE_E], s_part1[4][TILE_E];
    __shared__ int   s_y[4][TILE_E];     // 4-deep ring: write(t+1) never races read(t)
    __shared__ double s_dsum;

    const int tid  = threadIdx.x;
    const int lane = tid & 31;
    const int warp = tid >> 5;

    const uint32_t dynb = smem_u32(dyn);
    const uint32_t base = (dynb + 255u) & ~255u;
    const uint32_t Bsm  = base;
    const uint32_t Asm0 = base + B_BYTES;

    if (tid == 0) s_dsum = 0.0;
    if (tid < NHID) {
        s_b1[tid]  = b1[tid];
        s_al[tid]  = alpha[tid];
        s_w20[tid] = W2[2 * tid];
        s_w21[tid] = W2[2 * tid + 1];
    }
    {   // stage W1 image
        char* dst = dyn + (base - dynb);
        const int4* s = reinterpret_cast<const int4*>(g_w1_img);
        int4* d = reinterpret_cast<int4*>(dst);
        for (int i = tid; i < B_BYTES / 16; i += THREADS) d[i] = s[i];
    }

    const float bias0 = b2[0], bias1 = b2[1];

    // gather identity
    const int g_el = tid >> 2, g_rem = tid & 3;
    const int g_h = g_rem >> 1, g_part = g_rem & 1;

    // 4x4 warp grid: warp tile m32 x n32
    const int warp_m = warp & 3, warp_n = warp >> 2;
    const int m_base = warp_m * 32, n_base = warp_n * 32;

    // A ldmatrix bases: i in {0,1} -> rows m_base + i*16 + (lane&15)
    uint32_t rowA[2]; int xA[2];
    #pragma unroll
    for (int i = 0; i < 2; ++i) {
        const int r = m_base + i * 16 + (lane & 15);
        rowA[i] = (uint32_t)r * 512u;
        xA[i]   = r & 7;
    }
    const int csA = lane >> 4;

    // B ldmatrix bases (x4.trans): row k=(lane&15), chunk cn = warp_n*4 + j2*2 + (lane>>4)
    uint32_t bBase[2];
    {
        const int kr = lane & 15;
        const int xB = lane & 7;
        #pragma unroll
        for (int j2 = 0; j2 < 2; ++j2) {
            const int cn = warp_n * 4 + j2 * 2 + (lane >> 4);
            const int cs = (cn & 8) | ((cn & 7) ^ xB);
            bBase[j2] = Bsm + (uint32_t)kr * 256u + (uint32_t)cs * 16u;
        }
    }

    const int grid = gridDim.x;
    double dsum = 0.0;

    // ---- pipeline warm-up ----
    int nidN = 0, yvN = 0;
    if (blockIdx.x < ntiles) {
        int nid0, yv0;
        prefetch_idx(blockIdx.x, E, row, col, label, g_el, g_h, g_rem, nid0, yv0);
        if (g_rem == 0) s_y[0][g_el] = yv0;
        gather_issue(Asm0, nid0, g_el, g_h, g_part);
        asm volatile("cp.async.commit_group;" ::: "memory");
        if (blockIdx.x + grid < ntiles)
            prefetch_idx(blockIdx.x + grid, E, row, col, label, g_el, g_h, g_rem, nidN, yvN);
    }

    int li = 0;
    for (int t = blockIdx.x; t < ntiles; t += grid, ++li) {
        const int buf = li & 1;
        const uint32_t Abuf = Asm0 + (uint32_t)buf * A_BYTES;
        const int tn = t + grid;

        if (tn < ntiles) {
            // dependency-free: nidN/yvN were loaded during previous tile's GEMM
            if (g_rem == 0) s_y[(li + 1) & 3][g_el] = yvN;
            gather_issue(Asm0 + (uint32_t)(buf ^ 1) * A_BYTES, nidN, g_el, g_h, g_part);
            asm volatile("cp.async.commit_group;" ::: "memory");
            asm volatile("cp.async.wait_group 1;" ::: "memory");
            if (t + 2 * grid < ntiles)
                prefetch_idx(t + 2 * grid, E, row, col, label, g_el, g_h, g_rem, nidN, yvN);
        } else {
            asm volatile("cp.async.wait_group 0;" ::: "memory");
        }
        __syncthreads();

        // ---- GEMM: 16 k-steps of m16n8k16, warp tile m32n32 ----
        float acc[2][4][4];
        #pragma unroll
        for (int i = 0; i < 2; ++i)
            #pragma unroll
            for (int j = 0; j < 4; ++j) {
                acc[i][j][0] = 0.f; acc[i][j][1] = 0.f;
                acc[i][j][2] = 0.f; acc[i][j][3] = 0.f;
            }

        #pragma unroll
        for (int ks = 0; ks < 16; ++ks) {
            uint32_t a[2][4];
            #pragma unroll
            for (int i = 0; i < 2; ++i) {
                const int c  = 2 * ks + csA;
                const int cs = (c & 24) | ((c & 7) ^ xA[i]);
                const uint32_t addr = Abuf + rowA[i] + (uint32_t)cs * 16u;
                asm volatile("ldmatrix.sync.aligned.m8n8.x4.shared.b16 {%0,%1,%2,%3}, [%4];"
                    : "=r"(a[i][0]), "=r"(a[i][1]), "=r"(a[i][2]), "=r"(a[i][3]) : "r"(addr));
            }
            uint32_t b[2][4];
            #pragma unroll
            for (int j2 = 0; j2 < 2; ++j2) {
                const uint32_t addr = bBase[j2] + (uint32_t)ks * 4096u;
                asm volatile("ldmatrix.sync.aligned.m8n8.x4.trans.shared.b16 {%0,%1,%2,%3}, [%4];"
                    : "=r"(b[j2][0]), "=r"(b[j2][1]), "=r"(b[j2][2]), "=r"(b[j2][3]) : "r"(addr));
            }
            #pragma unroll
            for (int i = 0; i < 2; ++i)
                #pragma unroll
                for (int j = 0; j < 4; ++j) {
                    const uint32_t bb0 = b[j >> 1][(j & 1) * 2];
                    const uint32_t bb1 = b[j >> 1][(j & 1) * 2 + 1];
                    asm volatile(
                        "mma.sync.aligned.m16n8k16.row.col.f32.bf16.bf16.f32 "
                        "{%0,%1,%2,%3}, {%4,%5,%6,%7}, {%8,%9}, {%0,%1,%2,%3};"
                        : "+f"(acc[i][j][0]), "+f"(acc[i][j][1]),
                          "+f"(acc[i][j][2]), "+f"(acc[i][j][3])
                        : "r"(a[i][0]), "r"(a[i][1]), "r"(a[i][2]), "r"(a[i][3]),
                          "r"(bb0), "r"(bb1));
                }
        }

        // ---- fragment epilogue: PReLU + 128->2 projection (no atomics) ----
        const int quad = lane >> 2, qlane = lane & 3;
        float pr0[4], pr1[4];
        #pragma unroll
        for (int i = 0; i < 4; ++i) { pr0[i] = 0.f; pr1[i] = 0.f; }

        #pragma unroll
        for (int j = 0; j < 4; ++j) {
            const int n = n_base + j * 8 + qlane * 2;
            const float bv0 = s_b1[n],  bv1 = s_b1[n + 1];
            const float av0 = s_al[n],  av1 = s_al[n + 1];
            const float wa0 = s_w20[n], wa1 = s_w20[n + 1];
            const float wb0 = s_w21[n], wb1 = s_w21[n + 1];
            #pragma unroll
            for (int i = 0; i < 2; ++i) {
                float h;
                h = acc[i][j][0] + bv0; h = h >= 0.f ? h : av0 * h;
                pr0[i*2]   = fmaf(h, wa0, pr0[i*2]);   pr1[i*2]   = fmaf(h, wb0, pr1[i*2]);
                h = acc[i][j][1] + bv1; h = h >= 0.f ? h : av1 * h;
                pr0[i*2]   = fmaf(h, wa1, pr0[i*2]);   pr1[i*2]   = fmaf(h, wb1, pr1[i*2]);
                h = acc[i][j][2] + bv0; h = h >= 0.f ? h : av0 * h;
                pr0[i*2+1] = fmaf(h, wa0, pr0[i*2+1]); pr1[i*2+1] = fmaf(h, wb0, pr1[i*2+1]);
                h = acc[i][j][3] + bv1; h = h >= 0.f ? h : av1 * h;
                pr0[i*2+1] = fmaf(h, wa1, pr0[i*2+1]); pr1[i*2+1] = fmaf(h, wb1, pr1[i*2+1]);
            }
        }
        #pragma unroll
        for (int i = 0; i < 4; ++i) {
            pr0[i] += __shfl_xor_sync(0xffffffffu, pr0[i], 1);
            pr0[i] += __shfl_xor_sync(0xffffffffu, pr0[i], 2);
            pr1[i] += __shfl_xor_sync(0xffffffffu, pr1[i], 1);
            pr1[i] += __shfl_xor_sync(0xffffffffu, pr1[i], 2);
        }
        if (qlane == 0) {
            #pragma unroll
            for (int i = 0; i < 2; ++i) {
                const int r0 = m_base + i * 16 + quad;
                s_part0[warp_n][r0]     = pr0[i*2];   s_part1[warp_n][r0]     = pr1[i*2];
                s_part0[warp_n][r0 + 8] = pr0[i*2+1]; s_part1[warp_n][r0 + 8] = pr1[i*2+1];
            }
        }
        __syncthreads();

        // ---- per-edge log-softmax + NLL (also the A-buffer release barrier) ----
        if (tid < TILE_E) {
            const int e = t * TILE_E + tid;
            if (e < E) {
                const float l0 = s_part0[0][tid] + s_part0[1][tid]
                               + s_part0[2][tid] + s_part0[3][tid] + bias0;
                const float l1 = s_part1[0][tid] + s_part1[1][tid]
                               + s_part1[2][tid] + s_part1[3][tid] + bias1;
                const int y   = s_y[li & 3][tid];
                const float mx  = fmaxf(l0, l1);
                const float lse = mx + log1pf(expf(-fabsf(l0 - l1)));
                dsum += (double)((y ? l1 : l0) - lse);
            }
        }
    }

    __syncthreads();
    if (tid < TILE_E) atomicAdd(&s_dsum, dsum);
    __syncthreads();
    if (tid == 0) atomicAdd(&g_loss_sum, s_dsum);
}

extern "C" void kernel_launch(void* const* d_in, const int* in_sizes, int n_in,
                              void* d_out, int out_size) {
    const float* feature = (const float*)d_in[0];
    const float* W1      = (const float*)d_in[1];
    const float* b1      = (const float*)d_in[2];
    const float* alpha   = (const float*)d_in[3];
    const float* W2      = (const float*)d_in[4];
    const float* b2      = (const float*)d_in[5];
    const int*   row     = (const int*)d_in[6];
    const int*   col     = (const int*)d_in[7];
    const int*   label   = (const int*)d_in[8];
    const int E  = in_sizes[6];
    const int nf = in_sizes[0];
    float* out = (float*)d_out;

    int sms = 148;
    cudaDeviceGetAttribute(&sms, cudaDevAttrMultiProcessorCount, 0);
    cudaFuncSetAttribute(hx_main_kernel,
                         cudaFuncAttributeMaxDynamicSharedMemorySize, DSMEM);

    hx_init_kernel<<<1, 1>>>();
    hx_prep_feat<<<(nf / 4 + 255) / 256, 256>>>(feature, nf / 4);
    hx_prep_w1<<<(KDIM * NHID) / 256, 256>>>(W1);

    const int ntiles = (E + TILE_E - 1) / TILE_E;
    hx_main_kernel<<<sms, THREADS, DSMEM>>>(b1, alpha, W2, b2, row, col, label, E, ntiles);
    hx_final_kernel<<<1, 1>>>(out, E);
}